// round 4
// baseline (speedup 1.0000x reference)
#include <cuda_runtime.h>
#include <cuda_bf16.h>

#define N_NODES 1000000

// 4 MB scratch for per-node exp-sums (static __device__ per allocation rules)
__device__ float g_rowsum[N_NODES];

__device__ __forceinline__ float et_of(float x) {
    // exp(leaky_relu(x, 0.01))
    float lr = x > 0.0f ? x : 0.01f * x;
    return __expf(lr);
}

__global__ void zero_rowsum_kernel() {
    int i = blockIdx.x * blockDim.x + threadIdx.x;
    // N_NODES divisible by 4
    if (i < N_NODES / 4) {
        reinterpret_cast<float4*>(g_rowsum)[i] = make_float4(0.f, 0.f, 0.f, 0.f);
    }
}

__global__ void accum_kernel(const int* __restrict__ row,
                             const float* __restrict__ attr,
                             int E) {
    long long i = (long long)(blockIdx.x * blockDim.x + threadIdx.x) * 4;
    if (i + 3 < E) {
        int4   r = *reinterpret_cast<const int4*>(row + i);
        float4 a = *reinterpret_cast<const float4*>(attr + i);
        atomicAdd(&g_rowsum[r.x], et_of(a.x));
        atomicAdd(&g_rowsum[r.y], et_of(a.y));
        atomicAdd(&g_rowsum[r.z], et_of(a.z));
        atomicAdd(&g_rowsum[r.w], et_of(a.w));
    } else {
        for (; i < E; i++) {
            atomicAdd(&g_rowsum[row[i]], et_of(attr[i]));
        }
    }
}

__global__ void norm_kernel(const int* __restrict__ row,
                            const float* __restrict__ attr,
                            float* __restrict__ out,
                            int E) {
    long long i = (long long)(blockIdx.x * blockDim.x + threadIdx.x) * 4;
    if (i + 3 < E) {
        int4   r = *reinterpret_cast<const int4*>(row + i);
        float4 a = *reinterpret_cast<const float4*>(attr + i);
        // rowsum gathers hit L2 (4 MB array, L2-resident)
        float s0 = g_rowsum[r.x];
        float s1 = g_rowsum[r.y];
        float s2 = g_rowsum[r.z];
        float s3 = g_rowsum[r.w];
        float4 o;
        o.x = __fdividef(et_of(a.x), s0);
        o.y = __fdividef(et_of(a.y), s1);
        o.z = __fdividef(et_of(a.z), s2);
        o.w = __fdividef(et_of(a.w), s3);
        *reinterpret_cast<float4*>(out + i) = o;
    } else {
        for (; i < E; i++) {
            out[i] = __fdividef(et_of(attr[i]), g_rowsum[row[i]]);
        }
    }
}

extern "C" void kernel_launch(void* const* d_in, const int* in_sizes, int n_in,
                              void* d_out, int out_size) {
    // metadata order: edge_index (int32 in practice — JAX x64 disabled — [2, E] row-major),
    //                 edge_attr (f32, [E]), N (scalar)
    const int*   edge_index = (const int*)d_in[0];
    const float* edge_attr  = (const float*)d_in[1];
    float*       out        = (float*)d_out;

    int E = in_sizes[1];               // edge_attr element count
    const int* row = edge_index;       // edge_index[0] = first E elements

    const int TPB = 256;
    int zero_blocks = (N_NODES / 4 + TPB - 1) / TPB;
    int edge_threads = (E + 3) / 4;
    int edge_blocks = (edge_threads + TPB - 1) / TPB;

    zero_rowsum_kernel<<<zero_blocks, TPB>>>();
    accum_kernel<<<edge_blocks, TPB>>>(row, edge_attr, E);
    norm_kernel<<<edge_blocks, TPB>>>(row, edge_attr, out, E);
}